// round 14
// baseline (speedup 1.0000x reference)
#include <cuda_runtime.h>
#include <cuda_bf16.h>
#include <math.h>
#include <stdint.h>

#define NWIN 1024
#define NTOK 64
#define CD   192
#define C3   576
#define NROW 65536
#define OUT_ELEMS 12582912
#define ATTN_SCALE 0.17677669529663687f

// ---------------- device scratch ----------------
static __device__ __align__(16) __nv_bfloat16 g_qbf[NROW * CD];
static __device__ __align__(16) __nv_bfloat16 g_kbf[NROW * CD];
static __device__ __align__(16) __nv_bfloat16 g_vth[NROW * CD];
static __device__ __align__(16) __nv_bfloat16 g_vtl[NROW * CD];
static __device__ __align__(16) __nv_bfloat16 g_xh[NROW * CD];
static __device__ __align__(16) __nv_bfloat16 g_xl[NROW * CD];
static __device__ __align__(16) __nv_bfloat16 g_avh[NROW * CD];
static __device__ __align__(16) __nv_bfloat16 g_avl[NROW * CD];
static __device__ __align__(16) __nv_bfloat16 g_wt_hi[C3 * CD];
static __device__ __align__(16) __nv_bfloat16 g_wt_lo[C3 * CD];
static __device__ __align__(16) __nv_bfloat16 g_pt_hi[CD * CD];
static __device__ __align__(16) __nv_bfloat16 g_pt_lo[CD * CD];

// ---------------- PTX helpers ----------------
__device__ __forceinline__ uint32_t smem_u32(const void* p) {
    uint32_t a;
    asm("{ .reg .u64 t; cvta.to.shared.u64 t, %1; cvt.u32.u64 %0, t; }"
        : "=r"(a) : "l"(p));
    return a;
}
__device__ __forceinline__ void mma_bf16(float* c, const uint32_t* a,
                                         const uint32_t* b) {
    asm volatile(
        "mma.sync.aligned.m16n8k16.row.col.f32.bf16.bf16.f32 "
        "{%0,%1,%2,%3}, {%4,%5,%6,%7}, {%8,%9}, {%0,%1,%2,%3};"
        : "+f"(c[0]), "+f"(c[1]), "+f"(c[2]), "+f"(c[3])
        : "r"(a[0]), "r"(a[1]), "r"(a[2]), "r"(a[3]), "r"(b[0]), "r"(b[1]));
}
__device__ __forceinline__ void cp_async16(uint32_t dst, const void* src) {
    asm volatile("cp.async.cg.shared.global [%0], [%1], 16;\n"
                 :: "r"(dst), "l"(src));
}
#define CP_COMMIT() asm volatile("cp.async.commit_group;\n" ::: "memory")
#define CP_WAIT(n)  asm volatile("cp.async.wait_group %0;\n" :: "n"(n) : "memory")

__device__ __forceinline__ uint32_t bf2_of(float x, float y) {
    __nv_bfloat162 h = __float22bfloat162_rn(make_float2(x, y));
    return *(uint32_t*)&h;
}
__device__ __forceinline__ uint32_t bf2_lo_of(float x, float y, uint32_t hi) {
    __nv_bfloat162 hb = *(__nv_bfloat162*)&hi;
    float2 hf = __bfloat1622float2(hb);
    __nv_bfloat162 l = __float22bfloat162_rn(make_float2(x - hf.x, y - hf.y));
    return *(uint32_t*)&l;
}

// ---------------------------------------------------------------------------
// Kernel 0: combined prep — x gather+split + weight transpose+split.
// ---------------------------------------------------------------------------
__global__ __launch_bounds__(256) void prep_all(const float* __restrict__ x,
                                                const float* __restrict__ qkv_w,
                                                const float* __restrict__ proj_w)
{
    if (blockIdx.x < 12288) {
        int idx = blockIdx.x * 256 + threadIdx.x;
        int m  = idx / 48;
        int c4 = idx - m * 48;
        int wbv = m >> 6, n = m & 63;
        int b  = wbv >> 8;
        int wh = (wbv >> 4) & 15;
        int ww = wbv & 15;
        int gh = (wh * 8 + (n >> 3) + 4) & 127;
        int gw = (ww * 8 + (n & 7) + 4) & 127;
        float4 v = __ldcs((const float4*)(x +
                    ((size_t)((b * 128 + gh) * 128 + gw)) * CD + c4 * 4));
        __nv_bfloat162 h01 = __float22bfloat162_rn(make_float2(v.x, v.y));
        __nv_bfloat162 h23 = __float22bfloat162_rn(make_float2(v.z, v.w));
        float2 f01 = __bfloat1622float2(h01);
        float2 f23 = __bfloat1622float2(h23);
        __nv_bfloat162 l01 = __float22bfloat162_rn(make_float2(v.x - f01.x, v.y - f01.y));
        __nv_bfloat162 l23 = __float22bfloat162_rn(make_float2(v.z - f23.x, v.w - f23.y));
        uint2 hh, ll;
        hh.x = *(uint32_t*)&h01; hh.y = *(uint32_t*)&h23;
        ll.x = *(uint32_t*)&l01; ll.y = *(uint32_t*)&l23;
        *(uint2*)(g_xh + (size_t)m * CD + c4 * 4) = hh;
        *(uint2*)(g_xl + (size_t)m * CD + c4 * 4) = ll;
    } else {
        int idx = (blockIdx.x - 12288) * 256 + threadIdx.x;
        if (idx < C3 * CD) {
            int n = idx / CD, k = idx - n * CD;
            float v = qkv_w[k * C3 + n];
            __nv_bfloat16 h = __float2bfloat16_rn(v);
            g_wt_hi[idx] = h;
            g_wt_lo[idx] = __float2bfloat16_rn(v - __bfloat162float(h));
        } else {
            int j = idx - C3 * CD;
            if (j < CD * CD) {
                int n = j / CD, k = j - n * CD;
                float v = proj_w[k * CD + n];
                __nv_bfloat16 h = __float2bfloat16_rn(v);
                g_pt_hi[j] = h;
                g_pt_lo[j] = __float2bfloat16_rn(v - __bfloat162float(h));
            }
        }
    }
}

// ---------------------------------------------------------------------------
// mma.sync GEMM, K-chunks of 32, 4-stage cp.async ring (6 chunks).
// Stage layout (24576 B each): Ah @0 (8K) | Al @8192 | Bh @16384 (4K) | Bl @20480.
// Swizzle: 16B slot s of 64B row r stored at slot s ^ ((r>>1)&3).
// MODE 0: merged qkv. bn 0..5 = q/k (single-pass bf16); bn 6..8 = v (x3 + LePE).
// MODE 2: proj (x3), scatter to output.
// ---------------------------------------------------------------------------
#define STG 24576
#define MM_SMEM  100864   // 4 stages + LePE tail

template<int MODE>
__global__ __launch_bounds__(256, 2) void mma_gemm(
    const float* __restrict__ bias,
    float* __restrict__ outp,
    const float* __restrict__ lepe_w,
    const float* __restrict__ lepe_b)
{
    extern __shared__ char sm[];
    const uint32_t smb = smem_u32(sm);
    float* stage = (float*)sm;

    const int t    = threadIdx.x;
    const int w    = t >> 5;
    const int lane = t & 31;
    const int bm   = blockIdx.x;
    const int bn   = blockIdx.y;
    const int wm   = w >> 1;
    const int wn   = w & 1;
    const int g    = lane >> 2;
    const int tg   = lane & 3;

    const bool x3 = (MODE == 2) || (bn >= 6);

    const __nv_bfloat16* ah = (MODE == 2) ? g_avh : g_xh;
    const __nv_bfloat16* al = (MODE == 2) ? g_avl : g_xl;
    const __nv_bfloat16* bhp = (MODE == 2) ? g_pt_hi : g_wt_hi;
    const __nv_bfloat16* blp = (MODE == 2) ? g_pt_lo : g_wt_lo;

    float* swb_s = (float*)(sm + 98304);
    float* slb_s = swb_s + 576;
    if (MODE == 0 && bn >= 6) {
        for (int idx = t; idx < 576; idx += 256)
            swb_s[idx] = lepe_w[(idx >> 6) * CD + (bn - 6) * 64 + (idx & 63)];
        if (t < 64) slb_s[t] = lepe_b[(bn - 6) * 64 + t];
    }

    // per-thread loader assignments (chunk-invariant)
    const int ar0 = t >> 2;               // A rows for q=0 (0..63) / q=1 (+64)
    const int asl = t & 3;                // slot
    const uint32_t a_dst0 =
        (uint32_t)(ar0 * 64 + ((asl ^ ((ar0 >> 1) & 3)) << 4));
    const uint32_t a_dst1 =
        (uint32_t)((ar0 + 64) * 64 + ((asl ^ (((ar0 + 64) >> 1) & 3)) << 4));
    const uint32_t b_dst =
        (uint32_t)(16384 + ar0 * 64 + ((asl ^ ((ar0 >> 1) & 3)) << 4));
    const size_t a_src0 = (size_t)(bm * 128 + ar0) * CD + asl * 8;
    const size_t a_src1 = (size_t)(bm * 128 + ar0 + 64) * CD + asl * 8;
    const size_t b_src  = (size_t)(bn * 64 + (t >> 2)) * CD + asl * 8;

    auto prefetch = [&](int c, int buf) {
        const uint32_t sb = smb + (uint32_t)buf * STG;
        const int co = c * 32;
        cp_async16(sb + a_dst0, ah + a_src0 + co);
        cp_async16(sb + a_dst1, ah + a_src1 + co);
        cp_async16(sb + b_dst,  bhp + b_src + co);
        if (x3) {
            cp_async16(sb + a_dst0 + 8192u, al + a_src0 + co);
            cp_async16(sb + a_dst1 + 8192u, al + a_src1 + co);
            cp_async16(sb + b_dst + 4096u,  blp + b_src + co);
        }
    };

    float acc[2][4][4] = {};

    prefetch(0, 0); CP_COMMIT();
    prefetch(1, 1); CP_COMMIT();
    prefetch(2, 2); CP_COMMIT();

    #pragma unroll
    for (int c = 0; c < 6; c++) {
        if (c < 4)      CP_WAIT(2);
        else if (c == 4) CP_WAIT(1);
        else             CP_WAIT(0);
        __syncthreads();

        const char* base = sm + (c & 3) * STG;

        #pragma unroll
        for (int ks = 0; ks < 2; ks++) {
            const int sl0 = 2 * ks, sl1 = 2 * ks + 1;
            const uint32_t tw = (uint32_t)(tg * 4);

            uint32_t Ahf[2][4], Alf[2][4];
            #pragma unroll
            for (int i = 0; i < 2; i++) {
                const int r0 = wm * 32 + i * 16 + g;
                const int r1 = r0 + 8;
                const uint32_t xr0 = (uint32_t)((r0 >> 1) & 3);
                const uint32_t xr1 = (uint32_t)((r1 >> 1) & 3);
                const uint32_t o00 = (uint32_t)(r0 * 64) + (((uint32_t)sl0 ^ xr0) << 4) + tw;
                const uint32_t o10 = (uint32_t)(r1 * 64) + (((uint32_t)sl0 ^ xr1) << 4) + tw;
                const uint32_t o01 = (uint32_t)(r0 * 64) + (((uint32_t)sl1 ^ xr0) << 4) + tw;
                const uint32_t o11 = (uint32_t)(r1 * 64) + (((uint32_t)sl1 ^ xr1) << 4) + tw;
                Ahf[i][0] = *(const uint32_t*)(base + o00);
                Ahf[i][1] = *(const uint32_t*)(base + o10);
                Ahf[i][2] = *(const uint32_t*)(base + o01);
                Ahf[i][3] = *(const uint32_t*)(base + o11);
                if (x3) {
                    Alf[i][0] = *(const uint32_t*)(base + 8192 + o00);
                    Alf[i][1] = *(const uint32_t*)(base + 8192 + o10);
                    Alf[i][2] = *(const uint32_t*)(base + 8192 + o01);
                    Alf[i][3] = *(const uint32_t*)(base + 8192 + o11);
                }
            }
            uint32_t Bhf[4][2], Blf[4][2];
            #pragma unroll
            for (int j = 0; j < 4; j++) {
                const int rB = wn * 32 + j * 8 + g;
                const uint32_t xrB = (uint32_t)((rB >> 1) & 3);
                const uint32_t ob0 = (uint32_t)(rB * 64) + (((uint32_t)sl0 ^ xrB) << 4) + tw;
                const uint32_t ob1 = (uint32_t)(rB * 64) + (((uint32_t)sl1 ^ xrB) << 4) + tw;
                Bhf[j][0] = *(const uint32_t*)(base + 16384 + ob0);
                Bhf[j][1] = *(const uint32_t*)(base + 16384 + ob1);
                if (x3) {
                    Blf[j][0] = *(const uint32_t*)(base + 20480 + ob0);
                    Blf[j][1] = *(const uint32_t*)(base + 20480 + ob1);
                }
            }
            if (x3) {
                #pragma unroll
                for (int i = 0; i < 2; i++)
                    #pragma unroll
                    for (int j = 0; j < 4; j++) {
                        mma_bf16(acc[i][j], Ahf[i], Bhf[j]);
                        mma_bf16(acc[i][j], Ahf[i], Blf[j]);
                        mma_bf16(acc[i][j], Alf[i], Bhf[j]);
                    }
            } else {
                #pragma unroll
                for (int i = 0; i < 2; i++)
                    #pragma unroll
                    for (int j = 0; j < 4; j++)
                        mma_bf16(acc[i][j], Ahf[i], Bhf[j]);
            }
        }
        __syncthreads();
        if (c + 3 < 6) { prefetch(c + 3, (c + 3) & 3); CP_COMMIT(); }
    }

    // ---- stage C to smem (stride 68 floats) ----
    #pragma unroll
    for (int i = 0; i < 2; i++) {
        int row0 = wm * 32 + i * 16 + g;
        #pragma unroll
        for (int j = 0; j < 4; j++) {
            int col = wn * 32 + j * 8 + 2 * tg;
            *(float2*)&stage[row0 * 68 + col] =
                make_float2(acc[i][j][0], acc[i][j][1]);
            *(float2*)&stage[(row0 + 8) * 68 + col] =
                make_float2(acc[i][j][2], acc[i][j][3]);
        }
    }
    __syncthreads();

    if (MODE == 0 && bn >= 6) {
        // ---- fused LePE + transpose epilogue (v columns) ----
        const int col = t & 63;
        const int rg  = t >> 6;
        const int w2  = rg >> 1;
        const int i0  = (rg & 1) * 4;
        const float vb = bias[bn * 64 + col];
        const float lb = slb_s[col];
        float wgt[9];
        #pragma unroll
        for (int k9 = 0; k9 < 9; k9++) wgt[k9] = swb_s[k9 * 64 + col];
        const float* srow = stage + (w2 * 64) * 68 + col;
        float prv[8], cur[8], nxt[8];
        #pragma unroll
        for (int j = 0; j < 8; j++) {
            prv[j] = (i0 == 0) ? 0.f : (srow[((i0 - 1) * 8 + j) * 68] + vb);
            cur[j] = srow[(i0 * 8 + j) * 68] + vb;
        }
        const size_t obase =
            ((size_t)(bm * 2 + w2) * CD + (bn - 6) * 64 + col) * 64;
        #pragma unroll
        for (int ir = 0; ir < 4; ir++) {
            const int i = i0 + ir;
            #pragma unroll
            for (int j = 0; j < 8; j++)
                nxt[j] = (i == 7) ? 0.f : (srow[((i + 1) * 8 + j) * 68] + vb);
            uint32_t hv[4], lv[4];
            #pragma unroll
            for (int jp = 0; jp < 4; jp++) {
                float vp2[2];
                #pragma unroll
                for (int u = 0; u < 2; u++) {
                    const int j = jp * 2 + u;
                    float a = lb;
                    a = fmaf(prv[j], wgt[1], a);
                    a = fmaf(cur[j], wgt[4], a);
                    a = fmaf(nxt[j], wgt[7], a);
                    if (j > 0) {
                        a = fmaf(prv[j - 1], wgt[0], a);
                        a = fmaf(cur[j - 1], wgt[3], a);
                        a = fmaf(nxt[j - 1], wgt[6], a);
                    }
                    if (j < 7) {
                        a = fmaf(prv[j + 1], wgt[2], a);
                        a = fmaf(cur[j + 1], wgt[5], a);
                        a = fmaf(nxt[j + 1], wgt[8], a);
                    }
                    vp2[u] = cur[j] + a;
                }
                hv[jp] = bf2_of(vp2[0], vp2[1]);
                lv[jp] = bf2_lo_of(vp2[0], vp2[1], hv[jp]);
            }
            *(uint4*)(g_vth + obase + i * 8) =
                make_uint4(hv[0], hv[1], hv[2], hv[3]);
            *(uint4*)(g_vtl + obase + i * 8) =
                make_uint4(lv[0], lv[1], lv[2], lv[3]);
            #pragma unroll
            for (int j = 0; j < 8; j++) { prv[j] = cur[j]; cur[j] = nxt[j]; }
        }
    } else {
        const int s = t & 15;
        float4 b4 = *(const float4*)(bias + bn * 64 + s * 4);
        #pragma unroll
        for (int it = 0; it < 8; it++) {
            int row = (t >> 4) + 16 * it;
            float4 v = *(float4*)&stage[row * 68 + s * 4];
            v.x += b4.x; v.y += b4.y; v.z += b4.z; v.w += b4.w;
            int m = bm * 128 + row;
            if (MODE == 0) {
                int colg = bn * 64 + s * 4;      // 0..383 (q/k region)
                if (colg < CD) {
                    uint2 o;
                    o.x = bf2_of(v.x * ATTN_SCALE, v.y * ATTN_SCALE);
                    o.y = bf2_of(v.z * ATTN_SCALE, v.w * ATTN_SCALE);
                    *(uint2*)(g_qbf + (size_t)m * CD + colg) = o;
                } else {
                    uint2 o;
                    o.x = bf2_of(v.x, v.y);
                    o.y = bf2_of(v.z, v.w);
                    *(uint2*)(g_kbf + (size_t)m * CD + (colg - CD)) = o;
                }
            } else {
                int wbv = m >> 6, n = m & 63;
                int b  = wbv >> 8;
                int wh = (wbv >> 4) & 15;
                int ww = wbv & 15;
                int gh = (wh * 8 + (n >> 3) + 4) & 127;
                int gw = (ww * 8 + (n & 7) + 4) & 127;
                __stcs((float4*)(outp + ((size_t)((b * 128 + gh) * 128 + gw)) * CD
                                 + bn * 64 + s * 4), v);
            }
        }
    }
}

// ---------------------------------------------------------------------------
// Kernel 2: tensor-core attention (round-13 passing version, unchanged).
// ---------------------------------------------------------------------------
#define SQ_OFF  0
#define SK_OFF  25600
#define SVT_H   51200
#define SVT_L   78848
#define ATTN_SMEM 106496

__global__ __launch_bounds__(384, 2) void attn4(
    const float* __restrict__ prev,
    float* __restrict__ out)
{
    extern __shared__ char sm[];
    const uint32_t smb = smem_u32(sm);

    const int t  = threadIdx.x;
    const int wb = blockIdx.x;

    const size_t wbase = (size_t)wb * (NTOK * CD);
    #pragma unroll
    for (int q = 0; q < 4; q++) {
        int idx = t + 384 * q;
        int row = idx / 24, slot = idx - row * 24;
        uint32_t d = (uint32_t)(row * 400 + slot * 16);
        cp_async16(smb + SQ_OFF + d, g_qbf + wbase + (size_t)idx * 8);
        cp_async16(smb + SK_OFF + d, g_kbf + wbase + (size_t)idx * 8);
        int c = idx >> 3, ch = idx & 7;
        uint32_t dv = (uint32_t)(c * 144 + ch * 16);
        cp_async16(smb + SVT_H + dv, g_vth + wbase + (size_t)idx * 8);
        cp_async16(smb + SVT_L + dv, g_vtl + wbase + (size_t)idx * 8);
    }
    CP_COMMIT();
    CP_WAIT(0);
    __syncthreads();

    const int w    = t >> 5;
    const int lane = t & 31;
    const int g    = lane >> 2;
    const int tg   = lane & 3;

    for (int tile = w; tile < 24; tile += 12) {
        const int h  = tile >> 2;
        const int mt = tile & 3;

        float acc[8][4];
        #pragma unroll
        for (int nt = 0; nt < 8; nt++)
            acc[nt][0] = acc[nt][1] = acc[nt][2] = acc[nt][3] = 0.f;
        #pragma unroll
        for (int ks = 0; ks < 2; ks++) {
            const uint32_t kb = (uint32_t)(h * 64 + ks * 32 + tg * 4);
            uint32_t A[4];
            const char* q0 = sm + SQ_OFF + (mt * 16 + g) * 400 + kb;
            A[0] = *(const uint32_t*)(q0);
            A[1] = *(const uint32_t*)(q0 + 8 * 400);
            A[2] = *(const uint32_t*)(q0 + 16);
            A[3] = *(const uint32_t*)(q0 + 8 * 400 + 16);
            #pragma unroll
            for (int nt = 0; nt < 8; nt++) {
                const char* k0 = sm + SK_OFF + (nt * 8 + g) * 400 + kb;
                uint32_t B[2] = { *(const uint32_t*)k0,
                                  *(const uint32_t*)(k0 + 16) };
                mma_bf16(acc[nt], A, B);
            }
        }

        const float* pr = prev + (((size_t)(wb * 6 + h)) * 64 + mt * 16) * 64;
        #pragma unroll
        for (int nt = 0; nt < 8; nt++) {
            float2 p0 = __ldcs((const float2*)(pr + g * 64 + nt * 8 + 2 * tg));
            float2 p1 = __ldcs((const float2*)(pr + (g + 8) * 64 + nt * 8 + 2 * tg));
            acc[nt][0] *= p0.x; acc[nt][1] *= p0.y;
            acc[nt][2] *= p1.x; acc[nt][3] *= p1.y;
        }

        float m0 = -1e30f, m1 = -1e30f;
        #pragma unroll
        for (int nt = 0; nt < 8; nt++) {
            m0 = fmaxf(m0, fmaxf(acc[nt][0], acc[nt][1]));
            m1 = fmaxf(m1, fmaxf(acc[nt][2], acc[nt][3]));
        }
        m0 = fmaxf(m0, __shfl_xor_sync(0xffffffffu, m0, 1));
        m0 = fmaxf(m0, __shfl_xor_sync(0xffffffffu, m0, 2));
        m1 = fmaxf(m1, __shfl_xor_sync(0xffffffffu, m1, 1));
        m1 = fmaxf(m1, __shfl_xor_sync(0xffffffffu, m1, 2));
        float s0 = 0.f, s1 = 0.f;
        #pragma unroll
        for (int nt = 0; nt < 8; nt++) {
            acc[nt][0] = __expf(acc[nt][0] - m0);
            acc[nt][1] = __expf(acc[nt][1] - m0);
            acc[nt][2] = __expf(acc[nt][2] - m1);
            acc[nt][3] = __expf(acc[nt][3] - m1);
            s0 += acc[nt][0] + acc[nt][1];
            s1 += acc[nt][2] + acc[nt][3];
        }
        s0 += __shfl_xor_sync(0xffffffffu, s0, 1);
        s0 += __shfl_xor_sync(0xffffffffu, s0, 2);
        s1 += __shfl_xor_sync(0xffffffffu, s1, 1);
        s1 += __shfl_xor_sync(0xffffffffu, s1, 2);
        const float i0 = 1.0f / s0, i1 = 1.0f / s1;

        float* ao = out + OUT_ELEMS + (((size_t)(wb * 6 + h)) * 64 + mt * 16) * 64;
        #pragma unroll
        for (int nt = 0; nt < 8; nt++) {
            acc[nt][0] *= i0; acc[nt][1] *= i0;
            acc[nt][2] *= i1; acc[nt][3] *= i1;
            __stcs((float2*)(ao + g * 64 + nt * 8 + 2 * tg),
                   make_float2(acc[nt][0], acc[nt][1]));
            __stcs((float2*)(ao + (g + 8) * 64 + nt * 8 + 2 * tg),
                   make_float2(acc[nt][2], acc[nt][3]));
        }

        float acc2[4][4];
        #pragma unroll
        for (int nt = 0; nt < 4; nt++)
            acc2[nt][0] = acc2[nt][1] = acc2[nt][2] = acc2[nt][3] = 0.f;
        #pragma unroll
        for (int ks = 0; ks < 4; ks++) {
            const int j0 = 2 * ks, j1 = 2 * ks + 1;
            uint32_t Ahf[4], Alf[4];
            Ahf[0] = bf2_of(acc[j0][0], acc[j0][1]);
            Alf[0] = bf2_lo_of(acc[j0][0], acc[j0][1], Ahf[0]);
            Ahf[1] = bf2_of(acc[j0][2], acc[j0][3]);
            Alf[1] = bf2_lo_of(acc[j0][2], acc[j0][3], Ahf[1]);
            Ahf[2] = bf2_of(acc[j1][0], acc[j1][1]);
            Alf[2] = bf2_lo_of(acc[j1][0], acc[j1][1], Ahf[2]);
            Ahf[3] = bf2_of(acc[j1][2], acc[j1][3]);
            Alf[3] = bf2_lo_of(acc[j1][2], acc[j1][3], Ahf[3]);
            const uint32_t jb = (uint32_t)(ks * 32 + tg * 4);
            #pragma unroll
            for (int nt = 0; nt < 4; nt++) {
                const char* vh = sm + SVT_H + (h * 32 + nt * 8 + g) * 144 + jb;
                const char* vl = sm + SVT_L + (h * 32 + nt * 8 + g) * 144 + jb;
                uint32_t Bh2[2] = { *(const uint32_t*)vh,
                                    *(const uint32_t*)(vh + 16) };
                uint32_t Bl2[2] = { *(const uint32_t*)vl,
                                    *(const uint32_t*)(vl + 16) };
                mma_bf16(acc2[nt], Ahf, Bh2);
                mma_bf16(acc2[nt], Ahf, Bl2);
                mma_bf16(acc2[nt], Alf, Bh2);
            }
        }

        const size_t r0 = (size_t)(wb * 64 + mt * 16 + g) * CD + h * 32;
        const size_t r1 = r0 + 8 * CD;
        #pragma unroll
        for (int nt = 0; nt < 4; nt++) {
            int col = nt * 8 + 2 * tg;
            uint32_t h0 = bf2_of(acc2[nt][0], acc2[nt][1]);
            uint32_t l0 = bf2_lo_of(acc2[nt][0], acc2[nt][1], h0);
            uint32_t h1 = bf2_of(acc2[nt][2], acc2[nt][3]);
            uint32_t l1 = bf2_lo_of(acc2[nt][2], acc2[nt][3], h1);
            *(uint32_t*)(g_avh + r0 + col) = h0;
            *(uint32_t*)(g_avl + r0 + col) = l0;
            *(uint32_t*)(g_avh + r1 + col) = h1;
            *(uint32_t*)(g_avl + r1 + col) = l1;
        }
    }
}

// ---------------------------------------------------------------------------
extern "C" void kernel_launch(void* const* d_in, const int* in_sizes, int n_in,
                              void* d_out, int out_size)
{
    const float* x      = (const float*)d_in[0];
    const float* prev   = (const float*)d_in[1];
    const float* qkv_w  = (const float*)d_in[2];
    const float* qkv_b  = (const float*)d_in[3];
    const float* proj_w = (const float*)d_in[4];
    const float* proj_b = (const float*)d_in[5];
    const float* lepe_w = (const float*)d_in[6];
    const float* lepe_b = (const float*)d_in[7];
    float* out = (float*)d_out;

    cudaFuncSetAttribute(attn4,
                         cudaFuncAttributeMaxDynamicSharedMemorySize, ATTN_SMEM);
    cudaFuncSetAttribute(mma_gemm<0>,
                         cudaFuncAttributeMaxDynamicSharedMemorySize, MM_SMEM);
    cudaFuncSetAttribute(mma_gemm<2>,
                         cudaFuncAttributeMaxDynamicSharedMemorySize, MM_SMEM);

    prep_all<<<12864, 256>>>(x, qkv_w, proj_w);
    mma_gemm<0><<<dim3(512, 9), 256, MM_SMEM>>>(qkv_b, nullptr, lepe_w, lepe_b);
    attn4<<<NWIN, 384, ATTN_SMEM>>>(prev, out);
    mma_gemm<2><<<dim3(512, 3), 256, MM_SMEM>>>(proj_b, out, nullptr, nullptr);
}

// round 16
// speedup vs baseline: 1.0804x; 1.0804x over previous
#include <cuda_runtime.h>
#include <cuda_bf16.h>
#include <math.h>
#include <stdint.h>

#define NWIN 1024
#define NTOK 64
#define CD   192
#define C3   576
#define NROW 65536
#define OUT_ELEMS 12582912
#define ATTN_SCALE 0.17677669529663687f

// ---------------- device scratch ----------------
static __device__ __align__(16) __nv_bfloat16 g_qbf[NROW * CD];  // q, bias+scaled
static __device__ __align__(16) __nv_bfloat16 g_kbf[NROW * CD];  // k, bias
static __device__ __align__(16) __nv_bfloat16 g_vth[NROW * CD];  // v'^T hi
static __device__ __align__(16) __nv_bfloat16 g_vtl[NROW * CD];  // v'^T lo
static __device__ __align__(16) __nv_bfloat16 g_xh[NROW * CD];
static __device__ __align__(16) __nv_bfloat16 g_xl[NROW * CD];
static __device__ __align__(16) __nv_bfloat16 g_avh[NROW * CD];
static __device__ __align__(16) __nv_bfloat16 g_avl[NROW * CD];
static __device__ __align__(16) __nv_bfloat16 g_wt_hi[C3 * CD];
static __device__ __align__(16) __nv_bfloat16 g_wt_lo[C3 * CD];
static __device__ __align__(16) __nv_bfloat16 g_pt_hi[CD * CD];
static __device__ __align__(16) __nv_bfloat16 g_pt_lo[CD * CD];

// ---------------- PTX helpers ----------------
__device__ __forceinline__ uint32_t smem_u32(const void* p) {
    uint32_t a;
    asm("{ .reg .u64 t; cvta.to.shared.u64 t, %1; cvt.u32.u64 %0, t; }"
        : "=r"(a) : "l"(p));
    return a;
}
__device__ __forceinline__ void mma_bf16(float* c, const uint32_t* a,
                                         const uint32_t* b) {
    asm volatile(
        "mma.sync.aligned.m16n8k16.row.col.f32.bf16.bf16.f32 "
        "{%0,%1,%2,%3}, {%4,%5,%6,%7}, {%8,%9}, {%0,%1,%2,%3};"
        : "+f"(c[0]), "+f"(c[1]), "+f"(c[2]), "+f"(c[3])
        : "r"(a[0]), "r"(a[1]), "r"(a[2]), "r"(a[3]), "r"(b[0]), "r"(b[1]));
}
__device__ __forceinline__ void cp_async16(uint32_t dst, const void* src) {
    asm volatile("cp.async.cg.shared.global [%0], [%1], 16;\n"
                 :: "r"(dst), "l"(src));
}
#define CP_COMMIT() asm volatile("cp.async.commit_group;\n" ::: "memory")
#define CP_WAIT(n)  asm volatile("cp.async.wait_group %0;\n" :: "n"(n) : "memory")

__device__ __forceinline__ uint32_t bf2_of(float x, float y) {
    __nv_bfloat162 h = __float22bfloat162_rn(make_float2(x, y));
    return *(uint32_t*)&h;
}
__device__ __forceinline__ uint32_t bf2_lo_of(float x, float y, uint32_t hi) {
    __nv_bfloat162 hb = *(__nv_bfloat162*)&hi;
    float2 hf = __bfloat1622float2(hb);
    __nv_bfloat162 l = __float22bfloat162_rn(make_float2(x - hf.x, y - hf.y));
    return *(uint32_t*)&l;
}

// ---------------------------------------------------------------------------
// Kernel 0a: weight pre-transpose + bf16 hi/lo split.
// ---------------------------------------------------------------------------
__global__ __launch_bounds__(256) void prep_w(const float* __restrict__ qkv_w,
                                              const float* __restrict__ proj_w)
{
    int idx = blockIdx.x * 256 + threadIdx.x;
    if (idx < C3 * CD) {
        int n = idx / CD, k = idx - n * CD;
        float v = qkv_w[k * C3 + n];
        __nv_bfloat16 h = __float2bfloat16_rn(v);
        g_wt_hi[idx] = h;
        g_wt_lo[idx] = __float2bfloat16_rn(v - __bfloat162float(h));
    } else {
        int j = idx - C3 * CD;
        if (j < CD * CD) {
            int n = j / CD, k = j - n * CD;
            float v = proj_w[k * CD + n];
            __nv_bfloat16 h = __float2bfloat16_rn(v);
            g_pt_hi[j] = h;
            g_pt_lo[j] = __float2bfloat16_rn(v - __bfloat162float(h));
        }
    }
}

// ---------------------------------------------------------------------------
// Kernel 0b: shifted-window gather of x + bf16 hi/lo split.
// ---------------------------------------------------------------------------
__global__ __launch_bounds__(256) void prep_x(const float* __restrict__ x)
{
    int idx = blockIdx.x * 256 + threadIdx.x;
    int m  = idx / 48;
    int c4 = idx - m * 48;
    int wbv = m >> 6, n = m & 63;
    int b  = wbv >> 8;
    int wh = (wbv >> 4) & 15;
    int ww = wbv & 15;
    int gh = (wh * 8 + (n >> 3) + 4) & 127;
    int gw = (ww * 8 + (n & 7) + 4) & 127;
    float4 v = *(const float4*)(x + ((size_t)((b * 128 + gh) * 128 + gw)) * CD
                                + c4 * 4);
    __nv_bfloat162 h01 = __float22bfloat162_rn(make_float2(v.x, v.y));
    __nv_bfloat162 h23 = __float22bfloat162_rn(make_float2(v.z, v.w));
    float2 f01 = __bfloat1622float2(h01);
    float2 f23 = __bfloat1622float2(h23);
    __nv_bfloat162 l01 = __float22bfloat162_rn(make_float2(v.x - f01.x, v.y - f01.y));
    __nv_bfloat162 l23 = __float22bfloat162_rn(make_float2(v.z - f23.x, v.w - f23.y));
    uint2 hh, ll;
    hh.x = *(uint32_t*)&h01; hh.y = *(uint32_t*)&h23;
    ll.x = *(uint32_t*)&l01; ll.y = *(uint32_t*)&l23;
    *(uint2*)(g_xh + (size_t)m * CD + c4 * 4) = hh;
    *(uint2*)(g_xl + (size_t)m * CD + c4 * 4) = ll;
}

// ---------------------------------------------------------------------------
// mma.sync GEMM with cp.async double buffering (round-12 proven core).
// MODE 0: q,k single-pass bf16.  MODE 1: v bf16x3 + fused LePE epilogue.
// MODE 2: proj bf16x3, scatter to output.
// ---------------------------------------------------------------------------
template<int MODE, int MINB>
__global__ __launch_bounds__(256, MINB) void mma_gemm(
    const float* __restrict__ bias,
    float* __restrict__ outp,
    const float* __restrict__ lepe_w,
    const float* __restrict__ lepe_b)
{
    extern __shared__ char sm[];
    const uint32_t smb = smem_u32(sm);
    float* stage = (float*)sm;

    constexpr bool X3    = (MODE != 0);
    constexpr int  BNOFF = (MODE == 1) ? 6 : 0;
    constexpr uint32_t ABS   = X3 ? 32768u : 16384u;
    constexpr uint32_t BBASE = X3 ? 65536u : 32768u;
    constexpr uint32_t BBS   = X3 ? 16384u : 8192u;

    const __nv_bfloat16* ah = (MODE == 2) ? g_avh : g_xh;
    const __nv_bfloat16* al = (MODE == 2) ? g_avl : g_xl;
    const __nv_bfloat16* bhp = (MODE == 2) ? g_pt_hi : g_wt_hi;
    const __nv_bfloat16* blp = (MODE == 2) ? g_pt_lo : g_wt_lo;

    const int t    = threadIdx.x;
    const int w    = t >> 5;
    const int lane = t & 31;
    const int bm   = blockIdx.x;
    const int bn   = blockIdx.y;
    const int wm   = w >> 1;
    const int wn   = w & 1;
    const int g    = lane >> 2;
    const int tg   = lane & 3;

    float* swb_s = (float*)(sm + 98304);
    float* slb_s = swb_s + 576;
    if (MODE == 1) {
        for (int idx = t; idx < 576; idx += 256)
            swb_s[idx] = lepe_w[(idx >> 6) * CD + bn * 64 + (idx & 63)];
        if (t < 64) slb_s[t] = lepe_b[bn * 64 + t];
    }

    auto prefetch = [&](int c, int buf) {
        const uint32_t aB = smb + buf * ABS;
        const uint32_t bB = smb + BBASE + buf * BBS;
        #pragma unroll
        for (int q = 0; q < 4; q++) {
            int idx = t + 256 * q;
            int row = idx >> 3, slot = idx & 7;
            uint32_t dst = aB + (uint32_t)(row * 128 + ((slot ^ (row & 7)) << 4));
            size_t src = (size_t)(bm * 128 + row) * CD + c * 64 + slot * 8;
            cp_async16(dst, ah + src);
            if (X3) cp_async16(dst + 16384u, al + src);
        }
        #pragma unroll
        for (int q = 0; q < 2; q++) {
            int idx = t + 256 * q;
            int row = idx >> 3, slot = idx & 7;
            uint32_t dst = bB + (uint32_t)(row * 128 + ((slot ^ (row & 7)) << 4));
            size_t src = (size_t)((BNOFF + bn) * 64 + row) * CD + c * 64 + slot * 8;
            cp_async16(dst, bhp + src);
            if (X3) cp_async16(dst + 8192u, blp + src);
        }
    };

    float acc[2][4][4] = {};

    prefetch(0, 0); CP_COMMIT();
    prefetch(1, 1); CP_COMMIT();

    #pragma unroll
    for (int c = 0; c < 3; c++) {
        if (c < 2) CP_WAIT(1); else CP_WAIT(0);
        __syncthreads();

        const char* Ah_s = sm + (c & 1) * ABS;
        const char* Al_s = Ah_s + 16384;
        const char* Bh_s = sm + BBASE + (c & 1) * BBS;
        const char* Bl_s = Bh_s + 8192;

        #pragma unroll
        for (int ks = 0; ks < 4; ks++) {
            const uint32_t s0 = (uint32_t)((2 * ks) ^ g) << 4;
            const uint32_t s1 = (uint32_t)((2 * ks + 1) ^ g) << 4;
            const uint32_t tw = (uint32_t)(tg * 4);

            uint32_t Ahf[2][4], Alf[2][4];
            #pragma unroll
            for (int i = 0; i < 2; i++) {
                const uint32_t rb = (uint32_t)((wm * 32 + i * 16 + g) * 128);
                Ahf[i][0] = *(const uint32_t*)(Ah_s + rb + s0 + tw);
                Ahf[i][1] = *(const uint32_t*)(Ah_s + rb + 1024 + s0 + tw);
                Ahf[i][2] = *(const uint32_t*)(Ah_s + rb + s1 + tw);
                Ahf[i][3] = *(const uint32_t*)(Ah_s + rb + 1024 + s1 + tw);
                if (X3) {
                    Alf[i][0] = *(const uint32_t*)(Al_s + rb + s0 + tw);
                    Alf[i][1] = *(const uint32_t*)(Al_s + rb + 1024 + s0 + tw);
                    Alf[i][2] = *(const uint32_t*)(Al_s + rb + s1 + tw);
                    Alf[i][3] = *(const uint32_t*)(Al_s + rb + 1024 + s1 + tw);
                }
            }
            uint32_t Bhf[4][2], Blf[4][2];
            #pragma unroll
            for (int j = 0; j < 4; j++) {
                const uint32_t nb = (uint32_t)((wn * 32 + j * 8 + g) * 128);
                Bhf[j][0] = *(const uint32_t*)(Bh_s + nb + s0 + tw);
                Bhf[j][1] = *(const uint32_t*)(Bh_s + nb + s1 + tw);
                if (X3) {
                    Blf[j][0] = *(const uint32_t*)(Bl_s + nb + s0 + tw);
                    Blf[j][1] = *(const uint32_t*)(Bl_s + nb + s1 + tw);
                }
            }
            #pragma unroll
            for (int i = 0; i < 2; i++)
                #pragma unroll
                for (int j = 0; j < 4; j++) {
                    mma_bf16(acc[i][j], Ahf[i], Bhf[j]);
                    if (X3) {
                        mma_bf16(acc[i][j], Ahf[i], Blf[j]);
                        mma_bf16(acc[i][j], Alf[i], Bhf[j]);
                    }
                }
        }
        __syncthreads();
        if (c + 2 < 3) { prefetch(c + 2, (c + 2) & 1); CP_COMMIT(); }
    }

    // ---- stage C to smem (stride 68 floats) ----
    #pragma unroll
    for (int i = 0; i < 2; i++) {
        int row0 = wm * 32 + i * 16 + g;
        #pragma unroll
        for (int j = 0; j < 4; j++) {
            int col = wn * 32 + j * 8 + 2 * tg;
            *(float2*)&stage[row0 * 68 + col] =
                make_float2(acc[i][j][0], acc[i][j][1]);
            *(float2*)&stage[(row0 + 8) * 68 + col] =
                make_float2(acc[i][j][2], acc[i][j][3]);
        }
    }
    __syncthreads();

    if (MODE == 1) {
        // ---- fused LePE + transpose epilogue ----
        const int col = t & 63;
        const int rg  = t >> 6;
        const int w2  = rg >> 1;
        const int i0  = (rg & 1) * 4;
        const float vb = bias[(BNOFF + bn) * 64 + col];
        const float lb = slb_s[col];
        float wgt[9];
        #pragma unroll
        for (int k9 = 0; k9 < 9; k9++) wgt[k9] = swb_s[k9 * 64 + col];
        const float* srow = stage + (w2 * 64) * 68 + col;
        float prv[8], cur[8], nxt[8];
        #pragma unroll
        for (int j = 0; j < 8; j++) {
            prv[j] = (i0 == 0) ? 0.f : (srow[((i0 - 1) * 8 + j) * 68] + vb);
            cur[j] = srow[(i0 * 8 + j) * 68] + vb;
        }
        const size_t obase =
            ((size_t)(bm * 2 + w2) * CD + bn * 64 + col) * 64;
        #pragma unroll
        for (int ir = 0; ir < 4; ir++) {
            const int i = i0 + ir;
            #pragma unroll
            for (int j = 0; j < 8; j++)
                nxt[j] = (i == 7) ? 0.f : (srow[((i + 1) * 8 + j) * 68] + vb);
            uint32_t hv[4], lv[4];
            #pragma unroll
            for (int jp = 0; jp < 4; jp++) {
                float vp2[2];
                #pragma unroll
                for (int u = 0; u < 2; u++) {
                    const int j = jp * 2 + u;
                    float a = lb;
                    a = fmaf(prv[j], wgt[1], a);
                    a = fmaf(cur[j], wgt[4], a);
                    a = fmaf(nxt[j], wgt[7], a);
                    if (j > 0) {
                        a = fmaf(prv[j - 1], wgt[0], a);
                        a = fmaf(cur[j - 1], wgt[3], a);
                        a = fmaf(nxt[j - 1], wgt[6], a);
                    }
                    if (j < 7) {
                        a = fmaf(prv[j + 1], wgt[2], a);
                        a = fmaf(cur[j + 1], wgt[5], a);
                        a = fmaf(nxt[j + 1], wgt[8], a);
                    }
                    vp2[u] = cur[j] + a;
                }
                hv[jp] = bf2_of(vp2[0], vp2[1]);
                lv[jp] = bf2_lo_of(vp2[0], vp2[1], hv[jp]);
            }
            *(uint4*)(g_vth + obase + i * 8) =
                make_uint4(hv[0], hv[1], hv[2], hv[3]);
            *(uint4*)(g_vtl + obase + i * 8) =
                make_uint4(lv[0], lv[1], lv[2], lv[3]);
            #pragma unroll
            for (int j = 0; j < 8; j++) { prv[j] = cur[j]; cur[j] = nxt[j]; }
        }
    } else {
        const int s = t & 15;
        float4 b4 = *(const float4*)(bias + (BNOFF + bn) * 64 + s * 4);
        #pragma unroll
        for (int it = 0; it < 8; it++) {
            int row = (t >> 4) + 16 * it;
            float4 v = *(float4*)&stage[row * 68 + s * 4];
            v.x += b4.x; v.y += b4.y; v.z += b4.z; v.w += b4.w;
            int m = bm * 128 + row;
            if (MODE == 0) {
                int colg = bn * 64 + s * 4;
                if (colg < CD) {
                    uint2 o;
                    o.x = bf2_of(v.x * ATTN_SCALE, v.y * ATTN_SCALE);
                    o.y = bf2_of(v.z * ATTN_SCALE, v.w * ATTN_SCALE);
                    *(uint2*)(g_qbf + (size_t)m * CD + colg) = o;
                } else {
                    uint2 o;
                    o.x = bf2_of(v.x, v.y);
                    o.y = bf2_of(v.z, v.w);
                    *(uint2*)(g_kbf + (size_t)m * CD + (colg - CD)) = o;
                }
            } else {
                int wbv = m >> 6, n = m & 63;
                int b  = wbv >> 8;
                int wh = (wbv >> 4) & 15;
                int ww = wbv & 15;
                int gh = (wh * 8 + (n >> 3) + 4) & 127;
                int gw = (ww * 8 + (n & 7) + 4) & 127;
                *(float4*)(outp + ((size_t)((b * 128 + gh) * 128 + gw)) * CD
                           + bn * 64 + s * 4) = v;
            }
        }
    }
}

// ---------------------------------------------------------------------------
// Kernel 2: tensor-core attention. Two cp.async groups: q/k waited before
// QK^T; v'^T waited only between first-tile softmax and first-tile AV.
// ---------------------------------------------------------------------------
#define SQ_OFF  0
#define SK_OFF  25600
#define SVT_H   51200
#define SVT_L   78848
#define ATTN_SMEM 106496

__global__ __launch_bounds__(384, 2) void attn4(
    const float* __restrict__ prev,
    float* __restrict__ out)
{
    extern __shared__ char sm[];
    const uint32_t smb = smem_u32(sm);

    const int t  = threadIdx.x;
    const int wb = blockIdx.x;

    const size_t wbase = (size_t)wb * (NTOK * CD);
    // group 0: q + k
    #pragma unroll
    for (int q = 0; q < 4; q++) {
        int idx = t + 384 * q;
        int row = idx / 24, slot = idx - row * 24;
        uint32_t d = (uint32_t)(row * 400 + slot * 16);
        cp_async16(smb + SQ_OFF + d, g_qbf + wbase + (size_t)idx * 8);
        cp_async16(smb + SK_OFF + d, g_kbf + wbase + (size_t)idx * 8);
    }
    CP_COMMIT();
    // group 1: v'^T hi/lo
    #pragma unroll
    for (int q = 0; q < 4; q++) {
        int idx = t + 384 * q;
        int c = idx >> 3, ch = idx & 7;
        uint32_t dv = (uint32_t)(c * 144 + ch * 16);
        cp_async16(smb + SVT_H + dv, g_vth + wbase + (size_t)idx * 8);
        cp_async16(smb + SVT_L + dv, g_vtl + wbase + (size_t)idx * 8);
    }
    CP_COMMIT();
    CP_WAIT(1);            // q/k resident
    __syncthreads();

    const int w    = t >> 5;
    const int lane = t & 31;
    const int g    = lane >> 2;
    const int tg   = lane & 3;

    #pragma unroll
    for (int it = 0; it < 2; it++) {
        const int tile = w + it * 12;
        const int h  = tile >> 2;
        const int mt = tile & 3;

        float acc[8][4];
        #pragma unroll
        for (int nt = 0; nt < 8; nt++)
            acc[nt][0] = acc[nt][1] = acc[nt][2] = acc[nt][3] = 0.f;
        #pragma unroll
        for (int ks = 0; ks < 2; ks++) {
            const uint32_t kb = (uint32_t)(h * 64 + ks * 32 + tg * 4);
            uint32_t A[4];
            const char* q0 = sm + SQ_OFF + (mt * 16 + g) * 400 + kb;
            A[0] = *(const uint32_t*)(q0);
            A[1] = *(const uint32_t*)(q0 + 8 * 400);
            A[2] = *(const uint32_t*)(q0 + 16);
            A[3] = *(const uint32_t*)(q0 + 8 * 400 + 16);
            #pragma unroll
            for (int nt = 0; nt < 8; nt++) {
                const char* k0 = sm + SK_OFF + (nt * 8 + g) * 400 + kb;
                uint32_t B[2] = { *(const uint32_t*)k0,
                                  *(const uint32_t*)(k0 + 16) };
                mma_bf16(acc[nt], A, B);
            }
        }

        const float* pr = prev + (((size_t)(wb * 6 + h)) * 64 + mt * 16) * 64;
        #pragma unroll
        for (int nt = 0; nt < 8; nt++) {
            float2 p0 = *(const float2*)(pr + g * 64 + nt * 8 + 2 * tg);
            float2 p1 = *(const float2*)(pr + (g + 8) * 64 + nt * 8 + 2 * tg);
            acc[nt][0] *= p0.x; acc[nt][1] *= p0.y;
            acc[nt][2] *= p1.x; acc[nt][3] *= p1.y;
        }

        float m0 = -1e30f, m1 = -1e30f;
        #pragma unroll
        for (int nt = 0; nt < 8; nt++) {
            m0 = fmaxf(m0, fmaxf(acc[nt][0], acc[nt][1]));
            m1 = fmaxf(m1, fmaxf(acc[nt][2], acc[nt][3]));
        }
        m0 = fmaxf(m0, __shfl_xor_sync(0xffffffffu, m0, 1));
        m0 = fmaxf(m0, __shfl_xor_sync(0xffffffffu, m0, 2));
        m1 = fmaxf(m1, __shfl_xor_sync(0xffffffffu, m1, 1));
        m1 = fmaxf(m1, __shfl_xor_sync(0xffffffffu, m1, 2));
        float s0 = 0.f, s1 = 0.f;
        #pragma unroll
        for (int nt = 0; nt < 8; nt++) {
            acc[nt][0] = __expf(acc[nt][0] - m0);
            acc[nt][1] = __expf(acc[nt][1] - m0);
            acc[nt][2] = __expf(acc[nt][2] - m1);
            acc[nt][3] = __expf(acc[nt][3] - m1);
            s0 += acc[nt][0] + acc[nt][1];
            s1 += acc[nt][2] + acc[nt][3];
        }
        s0 += __shfl_xor_sync(0xffffffffu, s0, 1);
        s0 += __shfl_xor_sync(0xffffffffu, s0, 2);
        s1 += __shfl_xor_sync(0xffffffffu, s1, 1);
        s1 += __shfl_xor_sync(0xffffffffu, s1, 2);
        const float i0 = 1.0f / s0, i1 = 1.0f / s1;

        float* ao = out + OUT_ELEMS + (((size_t)(wb * 6 + h)) * 64 + mt * 16) * 64;
        #pragma unroll
        for (int nt = 0; nt < 8; nt++) {
            acc[nt][0] *= i0; acc[nt][1] *= i0;
            acc[nt][2] *= i1; acc[nt][3] *= i1;
            *(float2*)(ao + g * 64 + nt * 8 + 2 * tg) =
                make_float2(acc[nt][0], acc[nt][1]);
            *(float2*)(ao + (g + 8) * 64 + nt * 8 + 2 * tg) =
                make_float2(acc[nt][2], acc[nt][3]);
        }

        if (it == 0) {         // v'^T needed from here on
            CP_WAIT(0);
            __syncthreads();
        }

        float acc2[4][4];
        #pragma unroll
        for (int nt = 0; nt < 4; nt++)
            acc2[nt][0] = acc2[nt][1] = acc2[nt][2] = acc2[nt][3] = 0.f;
        #pragma unroll
        for (int ks = 0; ks < 4; ks++) {
            const int j0 = 2 * ks, j1 = 2 * ks + 1;
            uint32_t Ahf[4], Alf[4];
            Ahf[0] = bf2_of(acc[j0][0], acc[j0][1]);
            Alf[0] = bf2_lo_of(acc[j0][0], acc[j0][1], Ahf[0]);
            Ahf[1] = bf2_of(acc[j0][2], acc[j0][3]);
            Alf[1] = bf2_lo_of(acc[j0][2], acc[j0][3], Ahf[1]);
            Ahf[2] = bf2_of(acc[j1][0], acc[j1][1]);
            Alf[2] = bf2_lo_of(acc[j1][0], acc[j1][1], Ahf[2]);
            Ahf[3] = bf2_of(acc[j1][2], acc[j1][3]);
            Alf[3] = bf2_lo_of(acc[j1][2], acc[j1][3], Ahf[3]);
            const uint32_t jb = (uint32_t)(ks * 32 + tg * 4);
            #pragma unroll
            for (int nt = 0; nt < 4; nt++) {
                const char* vh = sm + SVT_H + (h * 32 + nt * 8 + g) * 144 + jb;
                const char* vl = sm + SVT_L + (h * 32 + nt * 8 + g) * 144 + jb;
                uint32_t Bh2[2] = { *(const uint32_t*)vh,
                                    *(const uint32_t*)(vh + 16) };
                uint32_t Bl2[2] = { *(const uint32_t*)vl,
                                    *(const uint32_t*)(vl + 16) };
                mma_bf16(acc2[nt], Ahf, Bh2);
                mma_bf16(acc2[nt], Ahf, Bl2);
                mma_bf16(acc2[nt], Alf, Bh2);
            }
        }

        const size_t r0 = (size_t)(wb * 64 + mt * 16 + g) * CD + h * 32;
        const size_t r1 = r0 + 8 * CD;
        #pragma unroll
        for (int nt = 0; nt < 4; nt++) {
            int col = nt * 8 + 2 * tg;
            uint32_t h0 = bf2_of(acc2[nt][0], acc2[nt][1]);
            uint32_t l0 = bf2_lo_of(acc2[nt][0], acc2[nt][1], h0);
            uint32_t h1 = bf2_of(acc2[nt][2], acc2[nt][3]);
            uint32_t l1 = bf2_lo_of(acc2[nt][2], acc2[nt][3], h1);
            *(uint32_t*)(g_avh + r0 + col) = h0;
            *(uint32_t*)(g_avl + r0 + col) = l0;
            *(uint32_t*)(g_avh + r1 + col) = h1;
            *(uint32_t*)(g_avl + r1 + col) = l1;
        }
    }
}

// ---------------------------------------------------------------------------
extern "C" void kernel_launch(void* const* d_in, const int* in_sizes, int n_in,
                              void* d_out, int out_size)
{
    const float* x      = (const float*)d_in[0];
    const float* prev   = (const float*)d_in[1];
    const float* qkv_w  = (const float*)d_in[2];
    const float* qkv_b  = (const float*)d_in[3];
    const float* proj_w = (const float*)d_in[4];
    const float* proj_b = (const float*)d_in[5];
    const float* lepe_w = (const float*)d_in[6];
    const float* lepe_b = (const float*)d_in[7];
    float* out = (float*)d_out;

    cudaFuncSetAttribute(attn4,
                         cudaFuncAttributeMaxDynamicSharedMemorySize, ATTN_SMEM);
    cudaFuncSetAttribute(mma_gemm<0, 3>,
                         cudaFuncAttributeMaxDynamicSharedMemorySize, 49152);
    cudaFuncSetAttribute(mma_gemm<1, 2>,
                         cudaFuncAttributeMaxDynamicSharedMemorySize, 100864);
    cudaFuncSetAttribute(mma_gemm<2, 2>,
                         cudaFuncAttributeMaxDynamicSharedMemorySize, 98304);

    prep_w<<<576, 256>>>(qkv_w, proj_w);
    prep_x<<<12288, 256>>>(x);
    mma_gemm<0, 3><<<dim3(512, 6), 256, 49152>>>(qkv_b, nullptr, nullptr, nullptr);
    mma_gemm<1, 2><<<dim3(512, 3), 256, 100864>>>(qkv_b, nullptr, lepe_w, lepe_b);
    attn4<<<NWIN, 384, ATTN_SMEM>>>(prev, out);
    mma_gemm<2, 2><<<dim3(512, 3), 256, 98304>>>(proj_b, out, nullptr, nullptr);
}

// round 17
// speedup vs baseline: 1.1146x; 1.0316x over previous
#include <cuda_runtime.h>
#include <cuda_bf16.h>
#include <math.h>
#include <stdint.h>

#define NWIN 1024
#define NTOK 64
#define CD   192
#define C3   576
#define NROW 65536
#define OUT_ELEMS 12582912
#define ATTN_SCALE 0.17677669529663687f

// ---------------- device scratch ----------------
static __device__ __align__(16) __nv_bfloat16 g_qbf[NROW * CD];  // q, bias+scaled
static __device__ __align__(16) __nv_bfloat16 g_kbf[NROW * CD];  // k, bias
static __device__ __align__(16) __nv_bfloat16 g_vth[NROW * CD];  // v'^T hi
static __device__ __align__(16) __nv_bfloat16 g_vtl[NROW * CD];  // v'^T lo
static __device__ __align__(16) __nv_bfloat16 g_xh[NROW * CD];
static __device__ __align__(16) __nv_bfloat16 g_xl[NROW * CD];
static __device__ __align__(16) __nv_bfloat16 g_avh[NROW * CD];
static __device__ __align__(16) __nv_bfloat16 g_avl[NROW * CD];
static __device__ __align__(16) __nv_bfloat16 g_wt_hi[C3 * CD];
static __device__ __align__(16) __nv_bfloat16 g_wt_lo[C3 * CD];
static __device__ __align__(16) __nv_bfloat16 g_pt_hi[CD * CD];
static __device__ __align__(16) __nv_bfloat16 g_pt_lo[CD * CD];

// ---------------- PTX helpers ----------------
__device__ __forceinline__ uint32_t smem_u32(const void* p) {
    uint32_t a;
    asm("{ .reg .u64 t; cvta.to.shared.u64 t, %1; cvt.u32.u64 %0, t; }"
        : "=r"(a) : "l"(p));
    return a;
}
__device__ __forceinline__ void mma_bf16(float* c, const uint32_t* a,
                                         const uint32_t* b) {
    asm volatile(
        "mma.sync.aligned.m16n8k16.row.col.f32.bf16.bf16.f32 "
        "{%0,%1,%2,%3}, {%4,%5,%6,%7}, {%8,%9}, {%0,%1,%2,%3};"
        : "+f"(c[0]), "+f"(c[1]), "+f"(c[2]), "+f"(c[3])
        : "r"(a[0]), "r"(a[1]), "r"(a[2]), "r"(a[3]), "r"(b[0]), "r"(b[1]));
}
__device__ __forceinline__ void cp_async16(uint32_t dst, const void* src) {
    asm volatile("cp.async.cg.shared.global [%0], [%1], 16;\n"
                 :: "r"(dst), "l"(src));
}
#define CP_COMMIT() asm volatile("cp.async.commit_group;\n" ::: "memory")
#define CP_WAIT(n)  asm volatile("cp.async.wait_group %0;\n" :: "n"(n) : "memory")

__device__ __forceinline__ uint32_t bf2_of(float x, float y) {
    __nv_bfloat162 h = __float22bfloat162_rn(make_float2(x, y));
    return *(uint32_t*)&h;
}
__device__ __forceinline__ uint32_t bf2_lo_of(float x, float y, uint32_t hi) {
    __nv_bfloat162 hb = *(__nv_bfloat162*)&hi;
    float2 hf = __bfloat1622float2(hb);
    __nv_bfloat162 l = __float22bfloat162_rn(make_float2(x - hf.x, y - hf.y));
    return *(uint32_t*)&l;
}

// ---------------------------------------------------------------------------
// Kernel 0a: weight pre-transpose + bf16 hi/lo split.
// ---------------------------------------------------------------------------
__global__ __launch_bounds__(256) void prep_w(const float* __restrict__ qkv_w,
                                              const float* __restrict__ proj_w)
{
    int idx = blockIdx.x * 256 + threadIdx.x;
    if (idx < C3 * CD) {
        int n = idx / CD, k = idx - n * CD;
        float v = qkv_w[k * C3 + n];
        __nv_bfloat16 h = __float2bfloat16_rn(v);
        g_wt_hi[idx] = h;
        g_wt_lo[idx] = __float2bfloat16_rn(v - __bfloat162float(h));
    } else {
        int j = idx - C3 * CD;
        if (j < CD * CD) {
            int n = j / CD, k = j - n * CD;
            float v = proj_w[k * CD + n];
            __nv_bfloat16 h = __float2bfloat16_rn(v);
            g_pt_hi[j] = h;
            g_pt_lo[j] = __float2bfloat16_rn(v - __bfloat162float(h));
        }
    }
}

// ---------------------------------------------------------------------------
// Kernel 0b: shifted-window gather of x + bf16 hi/lo split.
// ---------------------------------------------------------------------------
__global__ __launch_bounds__(256) void prep_x(const float* __restrict__ x)
{
    int idx = blockIdx.x * 256 + threadIdx.x;
    int m  = idx / 48;
    int c4 = idx - m * 48;
    int wbv = m >> 6, n = m & 63;
    int b  = wbv >> 8;
    int wh = (wbv >> 4) & 15;
    int ww = wbv & 15;
    int gh = (wh * 8 + (n >> 3) + 4) & 127;
    int gw = (ww * 8 + (n & 7) + 4) & 127;
    float4 v = *(const float4*)(x + ((size_t)((b * 128 + gh) * 128 + gw)) * CD
                                + c4 * 4);
    __nv_bfloat162 h01 = __float22bfloat162_rn(make_float2(v.x, v.y));
    __nv_bfloat162 h23 = __float22bfloat162_rn(make_float2(v.z, v.w));
    float2 f01 = __bfloat1622float2(h01);
    float2 f23 = __bfloat1622float2(h23);
    __nv_bfloat162 l01 = __float22bfloat162_rn(make_float2(v.x - f01.x, v.y - f01.y));
    __nv_bfloat162 l23 = __float22bfloat162_rn(make_float2(v.z - f23.x, v.w - f23.y));
    uint2 hh, ll;
    hh.x = *(uint32_t*)&h01; hh.y = *(uint32_t*)&h23;
    ll.x = *(uint32_t*)&l01; ll.y = *(uint32_t*)&l23;
    *(uint2*)(g_xh + (size_t)m * CD + c4 * 4) = hh;
    *(uint2*)(g_xl + (size_t)m * CD + c4 * 4) = ll;
}

// ---------------------------------------------------------------------------
// mma.sync GEMM with cp.async double buffering (round-12 proven core).
// MODE 0: q,k single-pass bf16.  MODE 1: v bf16x3 + fused LePE epilogue.
// MODE 2: proj bf16x3, scatter to output.
// ---------------------------------------------------------------------------
template<int MODE, int MINB>
__global__ __launch_bounds__(256, MINB) void mma_gemm(
    const float* __restrict__ bias,
    float* __restrict__ outp,
    const float* __restrict__ lepe_w,
    const float* __restrict__ lepe_b)
{
    extern __shared__ char sm[];
    const uint32_t smb = smem_u32(sm);
    float* stage = (float*)sm;

    constexpr bool X3    = (MODE != 0);
    constexpr int  BNOFF = (MODE == 1) ? 6 : 0;
    constexpr uint32_t ABS   = X3 ? 32768u : 16384u;
    constexpr uint32_t BBASE = X3 ? 65536u : 32768u;
    constexpr uint32_t BBS   = X3 ? 16384u : 8192u;

    const __nv_bfloat16* ah = (MODE == 2) ? g_avh : g_xh;
    const __nv_bfloat16* al = (MODE == 2) ? g_avl : g_xl;
    const __nv_bfloat16* bhp = (MODE == 2) ? g_pt_hi : g_wt_hi;
    const __nv_bfloat16* blp = (MODE == 2) ? g_pt_lo : g_wt_lo;

    const int t    = threadIdx.x;
    const int w    = t >> 5;
    const int lane = t & 31;
    const int bm   = blockIdx.x;
    const int bn   = blockIdx.y;
    const int wm   = w >> 1;
    const int wn   = w & 1;
    const int g    = lane >> 2;
    const int tg   = lane & 3;

    float* swb_s = (float*)(sm + 98304);
    float* slb_s = swb_s + 576;
    if (MODE == 1) {
        for (int idx = t; idx < 576; idx += 256)
            swb_s[idx] = lepe_w[(idx >> 6) * CD + bn * 64 + (idx & 63)];
        if (t < 64) slb_s[t] = lepe_b[bn * 64 + t];
    }

    auto prefetch = [&](int c, int buf) {
        const uint32_t aB = smb + buf * ABS;
        const uint32_t bB = smb + BBASE + buf * BBS;
        #pragma unroll
        for (int q = 0; q < 4; q++) {
            int idx = t + 256 * q;
            int row = idx >> 3, slot = idx & 7;
            uint32_t dst = aB + (uint32_t)(row * 128 + ((slot ^ (row & 7)) << 4));
            size_t src = (size_t)(bm * 128 + row) * CD + c * 64 + slot * 8;
            cp_async16(dst, ah + src);
            if (X3) cp_async16(dst + 16384u, al + src);
        }
        #pragma unroll
        for (int q = 0; q < 2; q++) {
            int idx = t + 256 * q;
            int row = idx >> 3, slot = idx & 7;
            uint32_t dst = bB + (uint32_t)(row * 128 + ((slot ^ (row & 7)) << 4));
            size_t src = (size_t)((BNOFF + bn) * 64 + row) * CD + c * 64 + slot * 8;
            cp_async16(dst, bhp + src);
            if (X3) cp_async16(dst + 8192u, blp + src);
        }
    };

    float acc[2][4][4] = {};

    prefetch(0, 0); CP_COMMIT();
    prefetch(1, 1); CP_COMMIT();

    #pragma unroll
    for (int c = 0; c < 3; c++) {
        if (c < 2) CP_WAIT(1); else CP_WAIT(0);
        __syncthreads();

        const char* Ah_s = sm + (c & 1) * ABS;
        const char* Al_s = Ah_s + 16384;
        const char* Bh_s = sm + BBASE + (c & 1) * BBS;
        const char* Bl_s = Bh_s + 8192;

        #pragma unroll
        for (int ks = 0; ks < 4; ks++) {
            const uint32_t s0 = (uint32_t)((2 * ks) ^ g) << 4;
            const uint32_t s1 = (uint32_t)((2 * ks + 1) ^ g) << 4;
            const uint32_t tw = (uint32_t)(tg * 4);

            uint32_t Ahf[2][4], Alf[2][4];
            #pragma unroll
            for (int i = 0; i < 2; i++) {
                const uint32_t rb = (uint32_t)((wm * 32 + i * 16 + g) * 128);
                Ahf[i][0] = *(const uint32_t*)(Ah_s + rb + s0 + tw);
                Ahf[i][1] = *(const uint32_t*)(Ah_s + rb + 1024 + s0 + tw);
                Ahf[i][2] = *(const uint32_t*)(Ah_s + rb + s1 + tw);
                Ahf[i][3] = *(const uint32_t*)(Ah_s + rb + 1024 + s1 + tw);
                if (X3) {
                    Alf[i][0] = *(const uint32_t*)(Al_s + rb + s0 + tw);
                    Alf[i][1] = *(const uint32_t*)(Al_s + rb + 1024 + s0 + tw);
                    Alf[i][2] = *(const uint32_t*)(Al_s + rb + s1 + tw);
                    Alf[i][3] = *(const uint32_t*)(Al_s + rb + 1024 + s1 + tw);
                }
            }
            uint32_t Bhf[4][2], Blf[4][2];
            #pragma unroll
            for (int j = 0; j < 4; j++) {
                const uint32_t nb = (uint32_t)((wn * 32 + j * 8 + g) * 128);
                Bhf[j][0] = *(const uint32_t*)(Bh_s + nb + s0 + tw);
                Bhf[j][1] = *(const uint32_t*)(Bh_s + nb + s1 + tw);
                if (X3) {
                    Blf[j][0] = *(const uint32_t*)(Bl_s + nb + s0 + tw);
                    Blf[j][1] = *(const uint32_t*)(Bl_s + nb + s1 + tw);
                }
            }
            #pragma unroll
            for (int i = 0; i < 2; i++)
                #pragma unroll
                for (int j = 0; j < 4; j++) {
                    mma_bf16(acc[i][j], Ahf[i], Bhf[j]);
                    if (X3) {
                        mma_bf16(acc[i][j], Ahf[i], Blf[j]);
                        mma_bf16(acc[i][j], Alf[i], Bhf[j]);
                    }
                }
        }
        __syncthreads();
        if (c + 2 < 3) { prefetch(c + 2, (c + 2) & 1); CP_COMMIT(); }
    }

    // ---- stage C to smem (stride 68 floats) ----
    #pragma unroll
    for (int i = 0; i < 2; i++) {
        int row0 = wm * 32 + i * 16 + g;
        #pragma unroll
        for (int j = 0; j < 4; j++) {
            int col = wn * 32 + j * 8 + 2 * tg;
            *(float2*)&stage[row0 * 68 + col] =
                make_float2(acc[i][j][0], acc[i][j][1]);
            *(float2*)&stage[(row0 + 8) * 68 + col] =
                make_float2(acc[i][j][2], acc[i][j][3]);
        }
    }
    __syncthreads();

    if (MODE == 1) {
        // ---- fused LePE + transpose epilogue ----
        const int col = t & 63;
        const int rg  = t >> 6;
        const int w2  = rg >> 1;
        const int i0  = (rg & 1) * 4;
        const float vb = bias[(BNOFF + bn) * 64 + col];
        const float lb = slb_s[col];
        float wgt[9];
        #pragma unroll
        for (int k9 = 0; k9 < 9; k9++) wgt[k9] = swb_s[k9 * 64 + col];
        const float* srow = stage + (w2 * 64) * 68 + col;
        float prv[8], cur[8], nxt[8];
        #pragma unroll
        for (int j = 0; j < 8; j++) {
            prv[j] = (i0 == 0) ? 0.f : (srow[((i0 - 1) * 8 + j) * 68] + vb);
            cur[j] = srow[(i0 * 8 + j) * 68] + vb;
        }
        const size_t obase =
            ((size_t)(bm * 2 + w2) * CD + bn * 64 + col) * 64;
        #pragma unroll
        for (int ir = 0; ir < 4; ir++) {
            const int i = i0 + ir;
            #pragma unroll
            for (int j = 0; j < 8; j++)
                nxt[j] = (i == 7) ? 0.f : (srow[((i + 1) * 8 + j) * 68] + vb);
            uint32_t hv[4], lv[4];
            #pragma unroll
            for (int jp = 0; jp < 4; jp++) {
                float vp2[2];
                #pragma unroll
                for (int u = 0; u < 2; u++) {
                    const int j = jp * 2 + u;
                    float a = lb;
                    a = fmaf(prv[j], wgt[1], a);
                    a = fmaf(cur[j], wgt[4], a);
                    a = fmaf(nxt[j], wgt[7], a);
                    if (j > 0) {
                        a = fmaf(prv[j - 1], wgt[0], a);
                        a = fmaf(cur[j - 1], wgt[3], a);
                        a = fmaf(nxt[j - 1], wgt[6], a);
                    }
                    if (j < 7) {
                        a = fmaf(prv[j + 1], wgt[2], a);
                        a = fmaf(cur[j + 1], wgt[5], a);
                        a = fmaf(nxt[j + 1], wgt[8], a);
                    }
                    vp2[u] = cur[j] + a;
                }
                hv[jp] = bf2_of(vp2[0], vp2[1]);
                lv[jp] = bf2_lo_of(vp2[0], vp2[1], hv[jp]);
            }
            *(uint4*)(g_vth + obase + i * 8) =
                make_uint4(hv[0], hv[1], hv[2], hv[3]);
            *(uint4*)(g_vtl + obase + i * 8) =
                make_uint4(lv[0], lv[1], lv[2], lv[3]);
            #pragma unroll
            for (int j = 0; j < 8; j++) { prv[j] = cur[j]; cur[j] = nxt[j]; }
        }
    } else {
        const int s = t & 15;
        float4 b4 = *(const float4*)(bias + (BNOFF + bn) * 64 + s * 4);
        #pragma unroll
        for (int it = 0; it < 8; it++) {
            int row = (t >> 4) + 16 * it;
            float4 v = *(float4*)&stage[row * 68 + s * 4];
            v.x += b4.x; v.y += b4.y; v.z += b4.z; v.w += b4.w;
            int m = bm * 128 + row;
            if (MODE == 0) {
                int colg = bn * 64 + s * 4;
                if (colg < CD) {
                    uint2 o;
                    o.x = bf2_of(v.x * ATTN_SCALE, v.y * ATTN_SCALE);
                    o.y = bf2_of(v.z * ATTN_SCALE, v.w * ATTN_SCALE);
                    *(uint2*)(g_qbf + (size_t)m * CD + colg) = o;
                } else {
                    uint2 o;
                    o.x = bf2_of(v.x, v.y);
                    o.y = bf2_of(v.z, v.w);
                    *(uint2*)(g_kbf + (size_t)m * CD + (colg - CD)) = o;
                }
            } else {
                int wbv = m >> 6, n = m & 63;
                int b  = wbv >> 8;
                int wh = (wbv >> 4) & 15;
                int ww = wbv & 15;
                int gh = (wh * 8 + (n >> 3) + 4) & 127;
                int gw = (ww * 8 + (n & 7) + 4) & 127;
                *(float4*)(outp + ((size_t)((b * 128 + gh) * 128 + gw)) * CD
                           + bn * 64 + s * 4) = v;
            }
        }
    }
}

// ---------------------------------------------------------------------------
// Kernel 2: tensor-core attention (round-12 passing version: single burst).
// ---------------------------------------------------------------------------
#define SQ_OFF  0
#define SK_OFF  25600
#define SVT_H   51200
#define SVT_L   78848
#define ATTN_SMEM 106496

__global__ __launch_bounds__(384, 2) void attn4(
    const float* __restrict__ prev,
    float* __restrict__ out)
{
    extern __shared__ char sm[];
    const uint32_t smb = smem_u32(sm);

    const int t  = threadIdx.x;
    const int wb = blockIdx.x;

    const size_t wbase = (size_t)wb * (NTOK * CD);
    #pragma unroll
    for (int q = 0; q < 4; q++) {
        int idx = t + 384 * q;
        int row = idx / 24, slot = idx - row * 24;
        uint32_t d = (uint32_t)(row * 400 + slot * 16);
        cp_async16(smb + SQ_OFF + d, g_qbf + wbase + (size_t)idx * 8);
        cp_async16(smb + SK_OFF + d, g_kbf + wbase + (size_t)idx * 8);
        int c = idx >> 3, ch = idx & 7;
        uint32_t dv = (uint32_t)(c * 144 + ch * 16);
        cp_async16(smb + SVT_H + dv, g_vth + wbase + (size_t)idx * 8);
        cp_async16(smb + SVT_L + dv, g_vtl + wbase + (size_t)idx * 8);
    }
    CP_COMMIT();
    CP_WAIT(0);
    __syncthreads();

    const int w    = t >> 5;
    const int lane = t & 31;
    const int g    = lane >> 2;
    const int tg   = lane & 3;

    for (int tile = w; tile < 24; tile += 12) {
        const int h  = tile >> 2;
        const int mt = tile & 3;

        float acc[8][4];
        #pragma unroll
        for (int nt = 0; nt < 8; nt++)
            acc[nt][0] = acc[nt][1] = acc[nt][2] = acc[nt][3] = 0.f;
        #pragma unroll
        for (int ks = 0; ks < 2; ks++) {
            const uint32_t kb = (uint32_t)(h * 64 + ks * 32 + tg * 4);
            uint32_t A[4];
            const char* q0 = sm + SQ_OFF + (mt * 16 + g) * 400 + kb;
            A[0] = *(const uint32_t*)(q0);
            A[1] = *(const uint32_t*)(q0 + 8 * 400);
            A[2] = *(const uint32_t*)(q0 + 16);
            A[3] = *(const uint32_t*)(q0 + 8 * 400 + 16);
            #pragma unroll
            for (int nt = 0; nt < 8; nt++) {
                const char* k0 = sm + SK_OFF + (nt * 8 + g) * 400 + kb;
                uint32_t B[2] = { *(const uint32_t*)k0,
                                  *(const uint32_t*)(k0 + 16) };
                mma_bf16(acc[nt], A, B);
            }
        }

        const float* pr = prev + (((size_t)(wb * 6 + h)) * 64 + mt * 16) * 64;
        #pragma unroll
        for (int nt = 0; nt < 8; nt++) {
            float2 p0 = *(const float2*)(pr + g * 64 + nt * 8 + 2 * tg);
            float2 p1 = *(const float2*)(pr + (g + 8) * 64 + nt * 8 + 2 * tg);
            acc[nt][0] *= p0.x; acc[nt][1] *= p0.y;
            acc[nt][2] *= p1.x; acc[nt][3] *= p1.y;
        }

        float m0 = -1e30f, m1 = -1e30f;
        #pragma unroll
        for (int nt = 0; nt < 8; nt++) {
            m0 = fmaxf(m0, fmaxf(acc[nt][0], acc[nt][1]));
            m1 = fmaxf(m1, fmaxf(acc[nt][2], acc[nt][3]));
        }
        m0 = fmaxf(m0, __shfl_xor_sync(0xffffffffu, m0, 1));
        m0 = fmaxf(m0, __shfl_xor_sync(0xffffffffu, m0, 2));
        m1 = fmaxf(m1, __shfl_xor_sync(0xffffffffu, m1, 1));
        m1 = fmaxf(m1, __shfl_xor_sync(0xffffffffu, m1, 2));
        float s0 = 0.f, s1 = 0.f;
        #pragma unroll
        for (int nt = 0; nt < 8; nt++) {
            acc[nt][0] = __expf(acc[nt][0] - m0);
            acc[nt][1] = __expf(acc[nt][1] - m0);
            acc[nt][2] = __expf(acc[nt][2] - m1);
            acc[nt][3] = __expf(acc[nt][3] - m1);
            s0 += acc[nt][0] + acc[nt][1];
            s1 += acc[nt][2] + acc[nt][3];
        }
        s0 += __shfl_xor_sync(0xffffffffu, s0, 1);
        s0 += __shfl_xor_sync(0xffffffffu, s0, 2);
        s1 += __shfl_xor_sync(0xffffffffu, s1, 1);
        s1 += __shfl_xor_sync(0xffffffffu, s1, 2);
        const float i0 = 1.0f / s0, i1 = 1.0f / s1;

        float* ao = out + OUT_ELEMS + (((size_t)(wb * 6 + h)) * 64 + mt * 16) * 64;
        #pragma unroll
        for (int nt = 0; nt < 8; nt++) {
            acc[nt][0] *= i0; acc[nt][1] *= i0;
            acc[nt][2] *= i1; acc[nt][3] *= i1;
            *(float2*)(ao + g * 64 + nt * 8 + 2 * tg) =
                make_float2(acc[nt][0], acc[nt][1]);
            *(float2*)(ao + (g + 8) * 64 + nt * 8 + 2 * tg) =
                make_float2(acc[nt][2], acc[nt][3]);
        }

        float acc2[4][4];
        #pragma unroll
        for (int nt = 0; nt < 4; nt++)
            acc2[nt][0] = acc2[nt][1] = acc2[nt][2] = acc2[nt][3] = 0.f;
        #pragma unroll
        for (int ks = 0; ks < 4; ks++) {
            const int j0 = 2 * ks, j1 = 2 * ks + 1;
            uint32_t Ahf[4], Alf[4];
            Ahf[0] = bf2_of(acc[j0][0], acc[j0][1]);
            Alf[0] = bf2_lo_of(acc[j0][0], acc[j0][1], Ahf[0]);
            Ahf[1] = bf2_of(acc[j0][2], acc[j0][3]);
            Alf[1] = bf2_lo_of(acc[j0][2], acc[j0][3], Ahf[1]);
            Ahf[2] = bf2_of(acc[j1][0], acc[j1][1]);
            Alf[2] = bf2_lo_of(acc[j1][0], acc[j1][1], Ahf[2]);
            Ahf[3] = bf2_of(acc[j1][2], acc[j1][3]);
            Alf[3] = bf2_lo_of(acc[j1][2], acc[j1][3], Ahf[3]);
            const uint32_t jb = (uint32_t)(ks * 32 + tg * 4);
            #pragma unroll
            for (int nt = 0; nt < 4; nt++) {
                const char* vh = sm + SVT_H + (h * 32 + nt * 8 + g) * 144 + jb;
                const char* vl = sm + SVT_L + (h * 32 + nt * 8 + g) * 144 + jb;
                uint32_t Bh2[2] = { *(const uint32_t*)vh,
                                    *(const uint32_t*)(vh + 16) };
                uint32_t Bl2[2] = { *(const uint32_t*)vl,
                                    *(const uint32_t*)(vl + 16) };
                mma_bf16(acc2[nt], Ahf, Bh2);
                mma_bf16(acc2[nt], Ahf, Bl2);
                mma_bf16(acc2[nt], Alf, Bh2);
            }
        }

        const size_t r0 = (size_t)(wb * 64 + mt * 16 + g) * CD + h * 32;
        const size_t r1 = r0 + 8 * CD;
        #pragma unroll
        for (int nt = 0; nt < 4; nt++) {
            int col = nt * 8 + 2 * tg;
            uint32_t h0 = bf2_of(acc2[nt][0], acc2[nt][1]);
            uint32_t l0 = bf2_lo_of(acc2[nt][0], acc2[nt][1], h0);
            uint32_t h1 = bf2_of(acc2[nt][2], acc2[nt][3]);
            uint32_t l1 = bf2_lo_of(acc2[nt][2], acc2[nt][3], h1);
            *(uint32_t*)(g_avh + r0 + col) = h0;
            *(uint32_t*)(g_avl + r0 + col) = l0;
            *(uint32_t*)(g_avh + r1 + col) = h1;
            *(uint32_t*)(g_avl + r1 + col) = l1;
        }
    }
}

// ---------------------------------------------------------------------------
// Launch: fork mma<0> onto a side stream so it overlaps mma<1>.
// Streams/events are created per call (host-side only; no device allocation).
// ---------------------------------------------------------------------------
extern "C" void kernel_launch(void* const* d_in, const int* in_sizes, int n_in,
                              void* d_out, int out_size)
{
    const float* x      = (const float*)d_in[0];
    const float* prev   = (const float*)d_in[1];
    const float* qkv_w  = (const float*)d_in[2];
    const float* qkv_b  = (const float*)d_in[3];
    const float* proj_w = (const float*)d_in[4];
    const float* proj_b = (const float*)d_in[5];
    const float* lepe_w = (const float*)d_in[6];
    const float* lepe_b = (const float*)d_in[7];
    float* out = (float*)d_out;

    cudaFuncSetAttribute(attn4,
                         cudaFuncAttributeMaxDynamicSharedMemorySize, ATTN_SMEM);
    cudaFuncSetAttribute(mma_gemm<0, 3>,
                         cudaFuncAttributeMaxDynamicSharedMemorySize, 49152);
    cudaFuncSetAttribute(mma_gemm<1, 2>,
                         cudaFuncAttributeMaxDynamicSharedMemorySize, 100864);
    cudaFuncSetAttribute(mma_gemm<2, 2>,
                         cudaFuncAttributeMaxDynamicSharedMemorySize, 98304);

    cudaStream_t s2;
    cudaStreamCreateWithFlags(&s2, cudaStreamNonBlocking);
    cudaEvent_t eFork, eJoin;
    cudaEventCreateWithFlags(&eFork, cudaEventDisableTiming);
    cudaEventCreateWithFlags(&eJoin, cudaEventDisableTiming);

    prep_w<<<576, 256>>>(qkv_w, proj_w);
    prep_x<<<12288, 256>>>(x);

    // fork: q/k GEMM on s2 runs concurrently with v GEMM on the default stream
    cudaEventRecord(eFork, 0);
    cudaStreamWaitEvent(s2, eFork, 0);
    mma_gemm<0, 3><<<dim3(512, 6), 256, 49152, s2>>>(qkv_b, nullptr,
                                                     nullptr, nullptr);
    mma_gemm<1, 2><<<dim3(512, 3), 256, 100864>>>(qkv_b, nullptr,
                                                  lepe_w, lepe_b);
    // join
    cudaEventRecord(eJoin, s2);
    cudaStreamWaitEvent(0, eJoin, 0);

    attn4<<<NWIN, 384, ATTN_SMEM>>>(prev, out);
    mma_gemm<2, 2><<<dim3(512, 3), 256, 98304>>>(proj_b, out, nullptr, nullptr);
}